// round 1
// baseline (speedup 1.0000x reference)
#include <cuda_runtime.h>
#include <math.h>

// Problem constants (fixed by setup_inputs)
#define BSZ   8
#define LSEQ  2048
#define DMOD  1024
#define SDIM  256
#define MROWS (BSZ*LSEQ)   // 16384

// Scratch (static device globals — no allocation at runtime)
__device__ float g_bufA[(size_t)MROWS * SDIM];       // 16 MB
__device__ float g_bufB[(size_t)MROWS * SDIM];       // 16 MB
__device__ float g_G[4][SDIM * SDIM];                // 1 MB : (A^T)^{1,2,4,8}
__device__ float g_Y[(size_t)MROWS * DMOD];          // 64 MB : gelu(states @ C^T)

// ---------------------------------------------------------------------------
// G0 = A^T (256x256)
// ---------------------------------------------------------------------------
__global__ void transpose_kernel(const float* __restrict__ A, float* __restrict__ G) {
    int k = blockIdx.x;     // 0..255
    int n = threadIdx.x;    // 0..255
    G[k * SDIM + n] = A[n * SDIM + k];
}

// ---------------------------------------------------------------------------
// Out = In @ In  (256x256x256). One CTA per output row.
// ---------------------------------------------------------------------------
__global__ void matsq_kernel(const float* __restrict__ In, float* __restrict__ Out) {
    __shared__ float row[SDIM];
    int r = blockIdx.x;
    int n = threadIdx.x;
    row[n] = In[r * SDIM + n];
    __syncthreads();
    float acc = 0.f;
#pragma unroll 8
    for (int k = 0; k < SDIM; k++)
        acc = fmaf(row[k], In[k * SDIM + n], acc);
    Out[r * SDIM + n] = acc;
}

__device__ __forceinline__ float gelu_exact(float x) {
    return 0.5f * x * (1.0f + erff(x * 0.7071067811865476f));
}

// ---------------------------------------------------------------------------
// Generic fp32 GEMM, 128x128x16 tile, 256 threads, 8x8 microtile.
//   B_NT  : B operand given as [N,K] row-major (compute Cout = A @ B^T)
//   !B_NT : B operand given as [K,N] row-major (compute Cout = A @ B)
//   SHIFT : A rows are shifted by `delta` within each length-LSEQ sequence
//           (zero-fill at sequence start) and the UNSHIFTED A row is added in
//           the epilogue. Requires K == N == SDIM.
//   GELU  : apply exact-erf GELU in epilogue.
// Dimensions must be multiples of the tile (they are: 16384, 256/1024, 256/1024).
// ---------------------------------------------------------------------------
template <bool B_NT, bool SHIFT, bool GELU>
__global__ __launch_bounds__(256, 2) void sgemm_kernel(
    const float* __restrict__ A, const float* __restrict__ Bm,
    float* __restrict__ Cout, int M, int N, int K, int delta)
{
    const int BM = 128, BN = 128, BK = 16, TM = 8, TN = 8;
    __shared__ float As[BK][BM];
    __shared__ float Bs[BK][BN];

    int tid = threadIdx.x;
    int tx = tid & 15;        // 0..15
    int ty = tid >> 4;        // 0..15
    int bm = blockIdx.y * BM;
    int bn = blockIdx.x * BN;

    float acc[TM][TN];
#pragma unroll
    for (int i = 0; i < TM; i++)
#pragma unroll
        for (int j = 0; j < TN; j++) acc[i][j] = 0.f;

    // A-tile loader: each thread loads 2 float4 (rows aR, aR+64; cols aC..aC+3)
    int aR = tid >> 2;            // 0..63
    int aC = (tid & 3) * 4;       // 0,4,8,12

    for (int k0 = 0; k0 < K; k0 += BK) {
        // ---- load A tile (transposed into smem) ----
#pragma unroll
        for (int rr = 0; rr < 2; rr++) {
            int m  = aR + rr * 64;
            int gr = bm + m;
            float4 v;
            if (SHIFT) {
                int t = gr & (LSEQ - 1);
                if (t >= delta)
                    v = *(const float4*)(A + (size_t)(gr - delta) * K + k0 + aC);
                else
                    v = make_float4(0.f, 0.f, 0.f, 0.f);
            } else {
                v = *(const float4*)(A + (size_t)gr * K + k0 + aC);
            }
            As[aC + 0][m] = v.x; As[aC + 1][m] = v.y;
            As[aC + 2][m] = v.z; As[aC + 3][m] = v.w;
        }
        // ---- load B tile ----
        if (B_NT) {
            // Bm [N,K]: Bs[k][n] = Bm[bn+n][k0+k]
            int nI = tid >> 2;          // 0..63
            int kI = (tid & 3) * 4;
#pragma unroll
            for (int rr = 0; rr < 2; rr++) {
                int n = nI + rr * 64;
                float4 v = *(const float4*)(Bm + (size_t)(bn + n) * K + k0 + kI);
                Bs[kI + 0][n] = v.x; Bs[kI + 1][n] = v.y;
                Bs[kI + 2][n] = v.z; Bs[kI + 3][n] = v.w;
            }
        } else {
            // Bm [K,N]: Bs[k][n] = Bm[k0+k][bn+n]
            int kI = tid >> 5;          // 0..7
            int nI = (tid & 31) * 4;    // 0..124
#pragma unroll
            for (int rr = 0; rr < 2; rr++) {
                int k = kI + rr * 8;
                float4 v = *(const float4*)(Bm + (size_t)(k0 + k) * N + bn + nI);
                *(float4*)(&Bs[k][nI]) = v;
            }
        }
        __syncthreads();

        // ---- compute ----
#pragma unroll
        for (int k = 0; k < BK; k++) {
            float rm[TM], rn[TN];
#pragma unroll
            for (int i = 0; i < TM; i++) rm[i] = As[k][ty * TM + i];
#pragma unroll
            for (int j = 0; j < TN; j++) rn[j] = Bs[k][tx * TN + j];
#pragma unroll
            for (int i = 0; i < TM; i++)
#pragma unroll
                for (int j = 0; j < TN; j++)
                    acc[i][j] = fmaf(rm[i], rn[j], acc[i][j]);
        }
        __syncthreads();
    }

    // ---- epilogue ----
#pragma unroll
    for (int i = 0; i < TM; i++) {
        int r = bm + ty * TM + i;
#pragma unroll
        for (int j = 0; j < TN; j += 4) {
            int c = bn + tx * TN + j;
            float4 v = make_float4(acc[i][j], acc[i][j + 1], acc[i][j + 2], acc[i][j + 3]);
            if (SHIFT) {
                // add unshifted input row (K == N here)
                float4 a = *(const float4*)(A + (size_t)r * N + c);
                v.x += a.x; v.y += a.y; v.z += a.z; v.w += a.w;
            }
            if (GELU) {
                v.x = gelu_exact(v.x); v.y = gelu_exact(v.y);
                v.z = gelu_exact(v.z); v.w = gelu_exact(v.w);
            }
            *(float4*)(Cout + (size_t)r * N + c) = v;
        }
    }
}

// ---------------------------------------------------------------------------
// LayerNorm over D=1024 per row; 256 threads, 4 elems/thread (float4).
// ---------------------------------------------------------------------------
__global__ void ln_kernel(const float* __restrict__ Y,
                          const float* __restrict__ gamma,
                          const float* __restrict__ beta,
                          float* __restrict__ Out)
{
    int r = blockIdx.x;
    const float* row = Y + (size_t)r * DMOD;
    int tid = threadIdx.x;

    float4 v = *(const float4*)(row + tid * 4);
    float s  = v.x + v.y + v.z + v.w;
    float sq = v.x * v.x + v.y * v.y + v.z * v.z + v.w * v.w;
#pragma unroll
    for (int o = 16; o > 0; o >>= 1) {
        s  += __shfl_xor_sync(0xffffffffu, s, o);
        sq += __shfl_xor_sync(0xffffffffu, sq, o);
    }
    __shared__ float ws[8], wq[8];
    int w = tid >> 5, l = tid & 31;
    if (l == 0) { ws[w] = s; wq[w] = sq; }
    __syncthreads();
    if (w == 0) {
        float a = (l < 8) ? ws[l] : 0.f;
        float b = (l < 8) ? wq[l] : 0.f;
#pragma unroll
        for (int o = 4; o > 0; o >>= 1) {
            a += __shfl_xor_sync(0xffffffffu, a, o);
            b += __shfl_xor_sync(0xffffffffu, b, o);
        }
        if (l == 0) { ws[0] = a; wq[0] = b; }
    }
    __syncthreads();
    float mean = ws[0] * (1.f / DMOD);
    float var  = wq[0] * (1.f / DMOD) - mean * mean;
    float rstd = rsqrtf(var + 1e-5f);

    float4 g  = *(const float4*)(gamma + tid * 4);
    float4 be = *(const float4*)(beta + tid * 4);
    float4 o;
    o.x = (v.x - mean) * rstd * g.x + be.x;
    o.y = (v.y - mean) * rstd * g.y + be.y;
    o.z = (v.z - mean) * rstd * g.z + be.z;
    o.w = (v.w - mean) * rstd * g.w + be.w;
    *(float4*)(Out + (size_t)r * DMOD + tid * 4) = o;
}

// ---------------------------------------------------------------------------
// kernel_launch
// inputs: x[8,2048,1024], A[256,256], B_mat[256,1024], C[1024,256],
//         gamma[1024], beta[1024]; output: [8,2048,1024] f32
// ---------------------------------------------------------------------------
extern "C" void kernel_launch(void* const* d_in, const int* in_sizes, int n_in,
                              void* d_out, int out_size)
{
    const float* x     = (const float*)d_in[0];
    const float* A     = (const float*)d_in[1];
    const float* Bmat  = (const float*)d_in[2];
    const float* C     = (const float*)d_in[3];
    const float* gamma = (const float*)d_in[4];
    const float* beta  = (const float*)d_in[5];
    float* out = (float*)d_out;

    float *bufA, *bufB, *G, *Y;
    cudaGetSymbolAddress((void**)&bufA, g_bufA);
    cudaGetSymbolAddress((void**)&bufB, g_bufB);
    cudaGetSymbolAddress((void**)&G,    g_G);
    cudaGetSymbolAddress((void**)&Y,    g_Y);
    float* G0 = G;
    float* G1 = G + SDIM * SDIM;
    float* G2 = G + 2 * SDIM * SDIM;
    float* G3 = G + 3 * SDIM * SDIM;

    // Powers of G = A^T : G, G^2, G^4, G^8
    transpose_kernel<<<SDIM, SDIM>>>(A, G0);
    matsq_kernel<<<SDIM, SDIM>>>(G0, G1);
    matsq_kernel<<<SDIM, SDIM>>>(G1, G2);
    matsq_kernel<<<SDIM, SDIM>>>(G2, G3);

    dim3 blk(256);
    // u = x @ B_mat^T   [16384,256]
    sgemm_kernel<true, false, false><<<dim3(SDIM / 128, MROWS / 128), blk>>>(
        x, Bmat, bufA, MROWS, SDIM, DMOD, 0);

    // scan doubling: w <- w + shift(w, d) @ G^d   for d = 1,2,4,8
    sgemm_kernel<false, true, false><<<dim3(SDIM / 128, MROWS / 128), blk>>>(
        bufA, G0, bufB, MROWS, SDIM, SDIM, 1);
    sgemm_kernel<false, true, false><<<dim3(SDIM / 128, MROWS / 128), blk>>>(
        bufB, G1, bufA, MROWS, SDIM, SDIM, 2);
    sgemm_kernel<false, true, false><<<dim3(SDIM / 128, MROWS / 128), blk>>>(
        bufA, G2, bufB, MROWS, SDIM, SDIM, 4);
    sgemm_kernel<false, true, false><<<dim3(SDIM / 128, MROWS / 128), blk>>>(
        bufB, G3, bufA, MROWS, SDIM, SDIM, 8);

    // y = gelu(states @ C^T)   [16384,1024]
    sgemm_kernel<true, false, true><<<dim3(DMOD / 128, MROWS / 128), blk>>>(
        bufA, C, Y, MROWS, DMOD, SDIM, 0);

    // LayerNorm
    ln_kernel<<<MROWS, 256>>>(Y, gamma, beta, out);
}

// round 3
// speedup vs baseline: 1.7099x; 1.7099x over previous
#include <cuda_runtime.h>
#include <cuda_bf16.h>
#include <mma.h>
#include <math.h>
#include <stdint.h>

using namespace nvcuda;

#define BSZ   8
#define LSEQ  2048
#define DMOD  1024
#define SDIM  256
#define MROWS (BSZ*LSEQ)   // 16384

// ---------------------------------------------------------------------------
// Static device scratch (no runtime allocation)
// ---------------------------------------------------------------------------
__device__ __align__(128) __nv_bfloat16 g_xh[(size_t)MROWS * DMOD];
__device__ __align__(128) __nv_bfloat16 g_xl[(size_t)MROWS * DMOD];
__device__ __align__(128) __nv_bfloat16 g_wh[2][(size_t)MROWS * SDIM];
__device__ __align__(128) __nv_bfloat16 g_wl[2][(size_t)MROWS * SDIM];
__device__ __align__(128) __nv_bfloat16 g_Bh[SDIM * DMOD];
__device__ __align__(128) __nv_bfloat16 g_Bl[SDIM * DMOD];
__device__ __align__(128) __nv_bfloat16 g_Ch[DMOD * SDIM];
__device__ __align__(128) __nv_bfloat16 g_Cl[DMOD * SDIM];
__device__ __align__(128) float         g_P[3][SDIM * SDIM];      // A^2,A^4,A^8 fp32
__device__ __align__(128) __nv_bfloat16 g_Ph[4][SDIM * SDIM];     // A,A2,A4,A8 hi
__device__ __align__(128) __nv_bfloat16 g_Pl[4][SDIM * SDIM];     // lo
__device__ __align__(128) float         g_Y[(size_t)MROWS * DMOD];

// ---------------------------------------------------------------------------
// Helpers
// ---------------------------------------------------------------------------
__global__ void matsq_kernel(const float* __restrict__ In, float* __restrict__ Out) {
    __shared__ float row[SDIM];
    int r = blockIdx.x, n = threadIdx.x;
    row[n] = In[r * SDIM + n];
    __syncthreads();
    float acc = 0.f;
#pragma unroll 8
    for (int k = 0; k < SDIM; k++) acc = fmaf(row[k], In[k * SDIM + n], acc);
    Out[r * SDIM + n] = acc;
}

// fp32 -> (hi, lo) bf16 split, 4 elems/thread
__global__ void split_kernel(const float* __restrict__ in,
                             __nv_bfloat16* __restrict__ h,
                             __nv_bfloat16* __restrict__ l, int n4) {
    int i = blockIdx.x * blockDim.x + threadIdx.x;
    if (i >= n4) return;
    float4 v = ((const float4*)in)[i];
    __nv_bfloat16 h0 = __float2bfloat16(v.x), h1 = __float2bfloat16(v.y);
    __nv_bfloat16 h2 = __float2bfloat16(v.z), h3 = __float2bfloat16(v.w);
    __nv_bfloat16 l0 = __float2bfloat16(v.x - __bfloat162float(h0));
    __nv_bfloat16 l1 = __float2bfloat16(v.y - __bfloat162float(h1));
    __nv_bfloat16 l2 = __float2bfloat16(v.z - __bfloat162float(h2));
    __nv_bfloat16 l3 = __float2bfloat16(v.w - __bfloat162float(h3));
    uint2 hv, lv;
    hv.x = (uint32_t)__bfloat16_as_ushort(h0) | ((uint32_t)__bfloat16_as_ushort(h1) << 16);
    hv.y = (uint32_t)__bfloat16_as_ushort(h2) | ((uint32_t)__bfloat16_as_ushort(h3) << 16);
    lv.x = (uint32_t)__bfloat16_as_ushort(l0) | ((uint32_t)__bfloat16_as_ushort(l1) << 16);
    lv.y = (uint32_t)__bfloat16_as_ushort(l2) | ((uint32_t)__bfloat16_as_ushort(l3) << 16);
    ((uint2*)h)[i] = hv;
    ((uint2*)l)[i] = lv;
}

__device__ __forceinline__ float gelu_exact(float x) {
    return 0.5f * x * (1.0f + erff(x * 0.7071067811865476f));
}

// ---------------------------------------------------------------------------
// WMMA (HMMA.16816, base sm_80+ ISA) GEMM with split-bf16 3-term products.
// C[128 x 128] tile = A[M,K] @ B[N,K]^T, fp32 accumulate.
//   STAGE 0: out = acc                    -> bf16 hi/lo   (width SDIM)
//   STAGE 1: out = acc + (addh+addl)[row] -> bf16 hi/lo   (A rows shifted by delta)
//   STAGE 2: out = gelu(acc)              -> fp32         (width DMOD)
// BM=BN=128, BK=32, 8 warps: warp tile 32(m) x 64(n).
// smem: double-buffered {Ah,Al,Bh,Bl}[128][40] bf16 (pad 8 -> conflict-free),
//       epilogue reuses smem as fp32 [128][132].
// ---------------------------------------------------------------------------
#define BKQ       32
#define LDT       40                       // padded tile row stride (elems)
#define TB        (128 * LDT * 2)          // one tile: 10240 B
#define STGB      (4 * TB)                 // Ah,Al,Bh,Bl : 40960 B
#define SMEM_SZ   (2 * STGB)               // 81920 B
#define LDC       132

template <int STAGE>
__global__ __launch_bounds__(256) void mma_gemm(
    const __nv_bfloat16* __restrict__ Ah, const __nv_bfloat16* __restrict__ Al,
    const __nv_bfloat16* __restrict__ Bh, const __nv_bfloat16* __restrict__ Bl,
    const __nv_bfloat16* __restrict__ addh, const __nv_bfloat16* __restrict__ addl,
    __nv_bfloat16* __restrict__ outh, __nv_bfloat16* __restrict__ outl,
    float* __restrict__ outf,
    int K, int delta)
{
    extern __shared__ char smem[];
    const int tid = threadIdx.x;
    const int bm = blockIdx.y * 128;
    const int nb = blockIdx.x * 128;
    const int NC = K / BKQ;

    const int w  = tid >> 5;
    const int wm = w & 3;          // 4 m-positions x 32 rows
    const int wn = w >> 2;         // 2 n-positions x 64 cols

    wmma::fragment<wmma::accumulator, 16, 16, 16, float> acc[2][4];
#pragma unroll
    for (int i = 0; i < 2; i++)
#pragma unroll
        for (int j = 0; j < 4; j++) wmma::fill_fragment(acc[i][j], 0.f);

    // loader indices: 512 uint4 chunks per tile, 2 per thread
    const int lr0 = tid >> 2;            // row/2 pairs: e>>2 gives row when e<512
    const int lcg = tid & 3;             // col group (8 bf16)

    auto load_tile = [&](int c, int buf) {
        char* base = smem + buf * STGB;
        __nv_bfloat16* sAh = (__nv_bfloat16*)(base);
        __nv_bfloat16* sAl = (__nv_bfloat16*)(base + TB);
        __nv_bfloat16* sBh = (__nv_bfloat16*)(base + 2 * TB);
        __nv_bfloat16* sBl = (__nv_bfloat16*)(base + 3 * TB);
        const int k0 = c * BKQ;
#pragma unroll
        for (int i = 0; i < 2; i++) {
            int row = lr0 + i * 64;
            int gr = bm + row;
            uint4 vh = make_uint4(0, 0, 0, 0), vl = vh;
            int t = gr & (LSEQ - 1);
            if (t >= delta) {
                size_t off = (size_t)(gr - delta) * K + k0 + lcg * 8;
                vh = *(const uint4*)(Ah + off);
                vl = *(const uint4*)(Al + off);
            }
            *(uint4*)(sAh + row * LDT + lcg * 8) = vh;
            *(uint4*)(sAl + row * LDT + lcg * 8) = vl;

            size_t boff = (size_t)(nb + row) * K + k0 + lcg * 8;
            *(uint4*)(sBh + row * LDT + lcg * 8) = *(const uint4*)(Bh + boff);
            *(uint4*)(sBl + row * LDT + lcg * 8) = *(const uint4*)(Bl + boff);
        }
    };

    load_tile(0, 0);
    __syncthreads();

    for (int c = 0; c < NC; c++) {
        const int b = c & 1;
        if (c + 1 < NC) load_tile(c + 1, b ^ 1);

        char* base = smem + b * STGB;
        const __nv_bfloat16* sAh = (const __nv_bfloat16*)(base);
        const __nv_bfloat16* sAl = (const __nv_bfloat16*)(base + TB);
        const __nv_bfloat16* sBh = (const __nv_bfloat16*)(base + 2 * TB);
        const __nv_bfloat16* sBl = (const __nv_bfloat16*)(base + 3 * TB);

#pragma unroll
        for (int kk = 0; kk < 2; kk++) {
            wmma::fragment<wmma::matrix_a, 16, 16, 16, __nv_bfloat16, wmma::row_major> fah[2], fal[2];
            wmma::fragment<wmma::matrix_b, 16, 16, 16, __nv_bfloat16, wmma::col_major> fbh[4], fbl[4];
#pragma unroll
            for (int i = 0; i < 2; i++) {
                const __nv_bfloat16* pa = sAh + (wm * 32 + i * 16) * LDT + kk * 16;
                wmma::load_matrix_sync(fah[i], pa, LDT);
                wmma::load_matrix_sync(fal[i], pa + 128 * LDT /*sAl - sAh*/, LDT);
            }
#pragma unroll
            for (int j = 0; j < 4; j++) {
                const __nv_bfloat16* pb = sBh + (wn * 64 + j * 16) * LDT + kk * 16;
                wmma::load_matrix_sync(fbh[j], pb, LDT);
                wmma::load_matrix_sync(fbl[j], pb + 128 * LDT /*sBl - sBh*/, LDT);
            }
#pragma unroll
            for (int i = 0; i < 2; i++)
#pragma unroll
                for (int j = 0; j < 4; j++) {
                    wmma::mma_sync(acc[i][j], fah[i], fbh[j], acc[i][j]);
                    wmma::mma_sync(acc[i][j], fah[i], fbl[j], acc[i][j]);
                    wmma::mma_sync(acc[i][j], fal[i], fbh[j], acc[i][j]);
                }
        }
        __syncthreads();
    }

    // ---- epilogue: stage through smem fp32 [128][132] ----
    float* Cs = (float*)smem;
#pragma unroll
    for (int i = 0; i < 2; i++)
#pragma unroll
        for (int j = 0; j < 4; j++)
            wmma::store_matrix_sync(Cs + (wm * 32 + i * 16) * LDC + wn * 64 + j * 16,
                                    acc[i][j], LDC, wmma::mem_row_major);
    __syncthreads();

    const int r = tid >> 1;                 // 0..127
    const int colbase = (tid & 1) * 64;     // 0 or 64
    const int gr = bm + r;
    const float* crow = Cs + r * LDC + colbase;

    if (STAGE == 2) {
#pragma unroll
        for (int g = 0; g < 16; g++) {
            float4 v = *(const float4*)(crow + g * 4);
            v.x = gelu_exact(v.x); v.y = gelu_exact(v.y);
            v.z = gelu_exact(v.z); v.w = gelu_exact(v.w);
            *(float4*)(outf + (size_t)gr * DMOD + nb + colbase + g * 4) = v;
        }
    } else {
#pragma unroll
        for (int g = 0; g < 8; g++) {
            float v[8];
#pragma unroll
            for (int q = 0; q < 8; q++) v[q] = crow[g * 8 + q];
            size_t gcol = (size_t)gr * SDIM + nb + colbase + g * 8;
            if (STAGE == 1) {
                uint4 hres = *(const uint4*)(addh + gcol);
                uint4 lres = *(const uint4*)(addl + gcol);
                const __nv_bfloat16* hp = (const __nv_bfloat16*)&hres;
                const __nv_bfloat16* lp = (const __nv_bfloat16*)&lres;
#pragma unroll
                for (int q = 0; q < 8; q++)
                    v[q] += __bfloat162float(hp[q]) + __bfloat162float(lp[q]);
            }
            __nv_bfloat16 hv[8], lv[8];
#pragma unroll
            for (int q = 0; q < 8; q++) {
                hv[q] = __float2bfloat16(v[q]);
                lv[q] = __float2bfloat16(v[q] - __bfloat162float(hv[q]));
            }
            *(uint4*)(outh + gcol) = *(const uint4*)hv;
            *(uint4*)(outl + gcol) = *(const uint4*)lv;
        }
    }
}

// ---------------------------------------------------------------------------
// LayerNorm over D=1024 per row
// ---------------------------------------------------------------------------
__global__ void ln_kernel(const float* __restrict__ Y,
                          const float* __restrict__ gamma,
                          const float* __restrict__ beta,
                          float* __restrict__ Out)
{
    int r = blockIdx.x;
    const float* row = Y + (size_t)r * DMOD;
    int tid = threadIdx.x;
    float4 v = *(const float4*)(row + tid * 4);
    float s = v.x + v.y + v.z + v.w;
    float sq = v.x * v.x + v.y * v.y + v.z * v.z + v.w * v.w;
#pragma unroll
    for (int o = 16; o > 0; o >>= 1) {
        s  += __shfl_xor_sync(0xffffffffu, s, o);
        sq += __shfl_xor_sync(0xffffffffu, sq, o);
    }
    __shared__ float ws[8], wq[8];
    int w = tid >> 5, l = tid & 31;
    if (l == 0) { ws[w] = s; wq[w] = sq; }
    __syncthreads();
    if (w == 0) {
        float a = (l < 8) ? ws[l] : 0.f;
        float b = (l < 8) ? wq[l] : 0.f;
#pragma unroll
        for (int o = 4; o > 0; o >>= 1) {
            a += __shfl_xor_sync(0xffffffffu, a, o);
            b += __shfl_xor_sync(0xffffffffu, b, o);
        }
        if (l == 0) { ws[0] = a; wq[0] = b; }
    }
    __syncthreads();
    float mean = ws[0] * (1.f / DMOD);
    float var  = wq[0] * (1.f / DMOD) - mean * mean;
    float rstd = rsqrtf(var + 1e-5f);
    float4 g  = *(const float4*)(gamma + tid * 4);
    float4 be = *(const float4*)(beta + tid * 4);
    float4 o;
    o.x = (v.x - mean) * rstd * g.x + be.x;
    o.y = (v.y - mean) * rstd * g.y + be.y;
    o.z = (v.z - mean) * rstd * g.z + be.z;
    o.w = (v.w - mean) * rstd * g.w + be.w;
    *(float4*)(Out + (size_t)r * DMOD + tid * 4) = o;
}

// ---------------------------------------------------------------------------
// kernel_launch
// ---------------------------------------------------------------------------
extern "C" void kernel_launch(void* const* d_in, const int* in_sizes, int n_in,
                              void* d_out, int out_size)
{
    const float* x     = (const float*)d_in[0];
    const float* A     = (const float*)d_in[1];
    const float* Bmat  = (const float*)d_in[2];
    const float* C     = (const float*)d_in[3];
    const float* gamma = (const float*)d_in[4];
    const float* beta  = (const float*)d_in[5];
    float* out = (float*)d_out;

    __nv_bfloat16 *xh, *xl, *wh0, *wl0, *wh1, *wl1, *Bh, *Bl, *Ch, *Cl, *Ph, *Pl;
    float *P, *Y;
    cudaGetSymbolAddress((void**)&xh, g_xh);
    cudaGetSymbolAddress((void**)&xl, g_xl);
    cudaGetSymbolAddress((void**)&wh0, g_wh);   wh1 = wh0 + (size_t)MROWS * SDIM;
    cudaGetSymbolAddress((void**)&wl0, g_wl);   wl1 = wl0 + (size_t)MROWS * SDIM;
    cudaGetSymbolAddress((void**)&Bh, g_Bh);
    cudaGetSymbolAddress((void**)&Bl, g_Bl);
    cudaGetSymbolAddress((void**)&Ch, g_Ch);
    cudaGetSymbolAddress((void**)&Cl, g_Cl);
    cudaGetSymbolAddress((void**)&P,  g_P);
    cudaGetSymbolAddress((void**)&Ph, g_Ph);
    cudaGetSymbolAddress((void**)&Pl, g_Pl);
    cudaGetSymbolAddress((void**)&Y,  g_Y);

    cudaFuncSetAttribute(mma_gemm<0>, cudaFuncAttributeMaxDynamicSharedMemorySize, SMEM_SZ);
    cudaFuncSetAttribute(mma_gemm<1>, cudaFuncAttributeMaxDynamicSharedMemorySize, SMEM_SZ);
    cudaFuncSetAttribute(mma_gemm<2>, cudaFuncAttributeMaxDynamicSharedMemorySize, SMEM_SZ);

    // ---- prep: splits + matrix powers ----
    split_kernel<<<(MROWS * DMOD / 4 + 255) / 256, 256>>>(x, xh, xl, MROWS * DMOD / 4);
    split_kernel<<<(SDIM * DMOD / 4 + 255) / 256, 256>>>(Bmat, Bh, Bl, SDIM * DMOD / 4);
    split_kernel<<<(DMOD * SDIM / 4 + 255) / 256, 256>>>(C, Ch, Cl, DMOD * SDIM / 4);
    split_kernel<<<(SDIM * SDIM / 4 + 255) / 256, 256>>>(A, Ph, Pl, SDIM * SDIM / 4);
    matsq_kernel<<<SDIM, SDIM>>>(A, P);                                 // A^2
    matsq_kernel<<<SDIM, SDIM>>>(P, P + SDIM * SDIM);                   // A^4
    matsq_kernel<<<SDIM, SDIM>>>(P + SDIM * SDIM, P + 2 * SDIM * SDIM); // A^8
    for (int i = 0; i < 3; i++)
        split_kernel<<<(SDIM * SDIM / 4 + 255) / 256, 256>>>(
            P + (size_t)i * SDIM * SDIM,
            Ph + (size_t)(i + 1) * SDIM * SDIM,
            Pl + (size_t)(i + 1) * SDIM * SDIM, SDIM * SDIM / 4);

    // ---- GEMM1: u = x @ Bmat^T   [16384 x 256], K=1024 ----
    mma_gemm<0><<<dim3(SDIM / 128, MROWS / 128), 256, SMEM_SZ>>>(
        xh, xl, Bh, Bl, nullptr, nullptr, wh0, wl0, nullptr, DMOD, 0);

    // ---- scan doubling: w += shift(w, d) @ (A^d)^T,  d = 1,2,4,8 ----
    const int deltas[4] = {1, 2, 4, 8};
    __nv_bfloat16* whp[2] = {wh0, wh1};
    __nv_bfloat16* wlp[2] = {wl0, wl1};
    for (int s = 0; s < 4; s++) {
        __nv_bfloat16* ah = whp[s & 1];       __nv_bfloat16* al = wlp[s & 1];
        __nv_bfloat16* oh = whp[(s + 1) & 1]; __nv_bfloat16* ol = wlp[(s + 1) & 1];
        mma_gemm<1><<<dim3(SDIM / 128, MROWS / 128), 256, SMEM_SZ>>>(
            ah, al,
            Ph + (size_t)s * SDIM * SDIM, Pl + (size_t)s * SDIM * SDIM,
            ah, al, oh, ol, nullptr, SDIM, deltas[s]);
    }

    // ---- GEMM2: y = gelu(w @ C^T)   [16384 x 1024], K=256 ----
    mma_gemm<2><<<dim3(DMOD / 128, MROWS / 128), 256, SMEM_SZ>>>(
        whp[0], wlp[0], Ch, Cl, nullptr, nullptr, nullptr, nullptr, Y, SDIM, 0);

    // ---- LayerNorm ----
    ln_kernel<<<MROWS, 256>>>(Y, gamma, beta, out);
}

// round 4
// speedup vs baseline: 1.7389x; 1.0169x over previous
#include <cuda_runtime.h>
#include <cuda_bf16.h>
#include <mma.h>
#include <math.h>
#include <stdint.h>

using namespace nvcuda;

#define BSZ   8
#define LSEQ  2048
#define DMOD  1024
#define SDIM  256
#define MROWS (BSZ*LSEQ)   // 16384

// ---------------------------------------------------------------------------
// Static device scratch
// ---------------------------------------------------------------------------
__device__ __align__(128) __nv_bfloat16 g_wh[2][(size_t)MROWS * SDIM];
__device__ __align__(128) __nv_bfloat16 g_wl[2][(size_t)MROWS * SDIM];
__device__ __align__(128) __nv_bfloat16 g_Bh[SDIM * DMOD];
__device__ __align__(128) __nv_bfloat16 g_Bl[SDIM * DMOD];
__device__ __align__(128) __nv_bfloat16 g_Ch[DMOD * SDIM];
__device__ __align__(128) __nv_bfloat16 g_Cl[DMOD * SDIM];
__device__ __align__(128) float         g_P[3][SDIM * SDIM];      // A^2,A^4,A^8
__device__ __align__(128) __nv_bfloat16 g_Ph[4][SDIM * SDIM];     // A,A2,A4,A8 hi
__device__ __align__(128) __nv_bfloat16 g_Pl[4][SDIM * SDIM];     // lo
__device__ __align__(128) float         g_Y[(size_t)MROWS * DMOD];

// ---------------------------------------------------------------------------
// Helpers
// ---------------------------------------------------------------------------
__device__ __forceinline__ uint32_t smem_u32(const void* p) {
    uint32_t a;
    asm("{ .reg .u64 t; cvta.to.shared.u64 t, %1; cvt.u32.u64 %0, t; }" : "=r"(a) : "l"(p));
    return a;
}
__device__ __forceinline__ void cp16(uint32_t s, const void* g) {
    asm volatile("cp.async.cg.shared.global [%0], [%1], 16;" :: "r"(s), "l"(g));
}
__device__ __forceinline__ void cp16z(uint32_t s, const void* g, int sz) {
    asm volatile("cp.async.cg.shared.global [%0], [%1], 16, %2;" :: "r"(s), "l"(g), "r"(sz));
}
#define CP_COMMIT()   asm volatile("cp.async.commit_group;" ::: "memory")
#define CP_WAIT(n)    asm volatile("cp.async.wait_group %0;" :: "n"(n) : "memory")

__device__ __forceinline__ float gelu_exact(float x) {
    return 0.5f * x * (1.0f + erff(x * 0.7071067811865476f));
}

// fp32 -> (hi, lo) bf16 split (for small weight matrices)
__global__ void split_kernel(const float* __restrict__ in,
                             __nv_bfloat16* __restrict__ h,
                             __nv_bfloat16* __restrict__ l, int n4) {
    int i = blockIdx.x * blockDim.x + threadIdx.x;
    if (i >= n4) return;
    float4 v = ((const float4*)in)[i];
    __nv_bfloat16 h0 = __float2bfloat16(v.x), h1 = __float2bfloat16(v.y);
    __nv_bfloat16 h2 = __float2bfloat16(v.z), h3 = __float2bfloat16(v.w);
    __nv_bfloat16 l0 = __float2bfloat16(v.x - __bfloat162float(h0));
    __nv_bfloat16 l1 = __float2bfloat16(v.y - __bfloat162float(h1));
    __nv_bfloat16 l2 = __float2bfloat16(v.z - __bfloat162float(h2));
    __nv_bfloat16 l3 = __float2bfloat16(v.w - __bfloat162float(h3));
    uint2 hv, lv;
    hv.x = (uint32_t)__bfloat16_as_ushort(h0) | ((uint32_t)__bfloat16_as_ushort(h1) << 16);
    hv.y = (uint32_t)__bfloat16_as_ushort(h2) | ((uint32_t)__bfloat16_as_ushort(h3) << 16);
    lv.x = (uint32_t)__bfloat16_as_ushort(l0) | ((uint32_t)__bfloat16_as_ushort(l1) << 16);
    lv.y = (uint32_t)__bfloat16_as_ushort(l2) | ((uint32_t)__bfloat16_as_ushort(l3) << 16);
    ((uint2*)h)[i] = hv;
    ((uint2*)l)[i] = lv;
}

// ---------------------------------------------------------------------------
// Tiled fp32 matrix square: Out = In @ In  (256x256). Tile 64x64, BK=32.
// ---------------------------------------------------------------------------
__global__ __launch_bounds__(256) void matsq2(const float* __restrict__ In,
                                              float* __restrict__ Out) {
    __shared__ float sA[64][33];
    __shared__ float sB[32][65];
    const int tid = threadIdx.x;
    const int i0 = blockIdx.y * 64, j0 = blockIdx.x * 64;
    const int ty = tid >> 4, tx = tid & 15;     // 16x16 threads, 4x4 microtile
    float acc[4][4] = {};
    for (int k0 = 0; k0 < SDIM; k0 += 32) {
#pragma unroll
        for (int i = 0; i < 8; i++) {
            int e = tid + i * 256;
            int ar = e >> 5, ak = e & 31;
            sA[ar][ak] = In[(i0 + ar) * SDIM + k0 + ak];
            int br = e >> 6, bc = e & 63;
            if (i < 8 && e < 2048) sB[br][bc] = In[(k0 + br) * SDIM + j0 + bc];
        }
        __syncthreads();
#pragma unroll
        for (int k = 0; k < 32; k++) {
            float a[4], b[4];
#pragma unroll
            for (int q = 0; q < 4; q++) a[q] = sA[ty * 4 + q][k];
#pragma unroll
            for (int q = 0; q < 4; q++) b[q] = sB[k][tx * 4 + q];
#pragma unroll
            for (int q = 0; q < 4; q++)
#pragma unroll
                for (int r = 0; r < 4; r++) acc[q][r] = fmaf(a[q], b[r], acc[q][r]);
        }
        __syncthreads();
    }
#pragma unroll
    for (int q = 0; q < 4; q++)
#pragma unroll
        for (int r = 0; r < 4; r++)
            Out[(i0 + ty * 4 + q) * SDIM + j0 + tx * 4 + r] = acc[q][r];
}

// ---------------------------------------------------------------------------
// WMMA GEMM, cp.async double-buffered. C[128 x 256] = A[M,K] @ B[N,K]^T.
// 3-term split-bf16, fp32 accumulate. 8 warps, warp tile 64x64.
//   STAGE 0: A = x fp32 (split in the loader), out -> bf16 hi/lo (width 256)
//   STAGE 1: A = w bf16 hi/lo shifted by delta, out = acc + u   -> bf16 hi/lo
//   STAGE 2: A = w bf16 hi/lo, out = gelu(acc) -> fp32 (width DMOD)
// smem per pipeline stage: Ah(18KB) Al(18KB) Bh(36KB) Bl(36KB), 144B row stride.
// ---------------------------------------------------------------------------
#define BKQ      64
#define LROW     144                       // bytes per tile row (128 data + 16 pad)
#define A_H_OFF  0
#define A_L_OFF  18432
#define B_H_OFF  36864
#define B_L_OFF  73728
#define STAGE_B  110592
#define SMEM_SZ  (2 * STAGE_B)             // 221184 B
#define LDCE     260                        // epilogue fp32 stride (elems)

template <int STAGE>
__global__ __launch_bounds__(256, 1) void mma_gemm(
    const float* __restrict__ Xf,
    const __nv_bfloat16* __restrict__ Ah, const __nv_bfloat16* __restrict__ Al,
    const __nv_bfloat16* __restrict__ Bh, const __nv_bfloat16* __restrict__ Bl,
    const __nv_bfloat16* __restrict__ addh, const __nv_bfloat16* __restrict__ addl,
    __nv_bfloat16* __restrict__ outh, __nv_bfloat16* __restrict__ outl,
    float* __restrict__ outf,
    int K, int delta)
{
    extern __shared__ char smem[];
    const int tid = threadIdx.x;
    const int bm = blockIdx.y * 128;
    const int nb = blockIdx.x * 256;
    const int NC = K / BKQ;
    const uint32_t sb = smem_u32(smem);

    const int w  = tid >> 5;
    const int wm = w & 1;          // 2 m-positions x 64
    const int wn = w >> 1;         // 4 n-positions x 64

    wmma::fragment<wmma::accumulator, 16, 16, 16, float> acc[4][4];
#pragma unroll
    for (int i = 0; i < 4; i++)
#pragma unroll
        for (int j = 0; j < 4; j++) wmma::fill_fragment(acc[i][j], 0.f);

    auto load_tile = [&](int c, int buf) {
        const uint32_t base = sb + buf * STAGE_B;
        const int k0 = c * BKQ;
        if (STAGE == 0) {
            // A: x fp32 128x64, split to hi/lo in-register
#pragma unroll
            for (int i = 0; i < 8; i++) {
                int e = tid + i * 256;
                int row = e >> 4, cg = e & 15;
                float4 v = *(const float4*)(Xf + (size_t)(bm + row) * K + k0 + cg * 4);
                __nv_bfloat16 h0 = __float2bfloat16(v.x), h1 = __float2bfloat16(v.y);
                __nv_bfloat16 h2 = __float2bfloat16(v.z), h3 = __float2bfloat16(v.w);
                __nv_bfloat16 l0 = __float2bfloat16(v.x - __bfloat162float(h0));
                __nv_bfloat16 l1 = __float2bfloat16(v.y - __bfloat162float(h1));
                __nv_bfloat16 l2 = __float2bfloat16(v.z - __bfloat162float(h2));
                __nv_bfloat16 l3 = __float2bfloat16(v.w - __bfloat162float(h3));
                uint2 hv, lv;
                hv.x = (uint32_t)__bfloat16_as_ushort(h0) | ((uint32_t)__bfloat16_as_ushort(h1) << 16);
                hv.y = (uint32_t)__bfloat16_as_ushort(h2) | ((uint32_t)__bfloat16_as_ushort(h3) << 16);
                lv.x = (uint32_t)__bfloat16_as_ushort(l0) | ((uint32_t)__bfloat16_as_ushort(l1) << 16);
                lv.y = (uint32_t)__bfloat16_as_ushort(l2) | ((uint32_t)__bfloat16_as_ushort(l3) << 16);
                uint32_t so = row * LROW + cg * 8;
                *(uint2*)(smem + buf * STAGE_B + A_H_OFF + so) = hv;
                *(uint2*)(smem + buf * STAGE_B + A_L_OFF + so) = lv;
            }
        } else {
            // A: bf16 hi/lo 128x64, rows shifted by delta (zero-fill)
#pragma unroll
            for (int i = 0; i < 4; i++) {
                int e = tid + i * 256;
                int row = e >> 3, kc = e & 7;
                int gr = bm + row;
                int t = gr & (LSEQ - 1);
                int sz = (t >= delta) ? 16 : 0;
                int srow = gr - (t >= delta ? delta : 0);
                size_t go = (size_t)srow * K + k0 + kc * 8;
                uint32_t so = base + row * LROW + kc * 16;
                cp16z(so + A_H_OFF, Ah + go, sz);
                cp16z(so + A_L_OFF, Al + go, sz);
            }
        }
        // B: bf16 hi/lo 256x64
#pragma unroll
        for (int i = 0; i < 8; i++) {
            int e = tid + i * 256;
            int row = e >> 3, kc = e & 7;
            size_t go = (size_t)(nb + row) * K + k0 + kc * 8;
            uint32_t so = base + row * LROW + kc * 16;
            cp16(so + B_H_OFF, Bh + go);
            cp16(so + B_L_OFF, Bl + go);
        }
        CP_COMMIT();
    };

    load_tile(0, 0);

    for (int c = 0; c < NC; c++) {
        const int b = c & 1;
        if (c + 1 < NC) { load_tile(c + 1, b ^ 1); CP_WAIT(1); }
        else            { CP_WAIT(0); }
        __syncthreads();

        const char* base = smem + b * STAGE_B;
        const __nv_bfloat16* sAh = (const __nv_bfloat16*)(base + A_H_OFF);
        const __nv_bfloat16* sAl = (const __nv_bfloat16*)(base + A_L_OFF);
        const __nv_bfloat16* sBh = (const __nv_bfloat16*)(base + B_H_OFF);
        const __nv_bfloat16* sBl = (const __nv_bfloat16*)(base + B_L_OFF);
        const int LDE = LROW / 2;   // 72 elems

#pragma unroll
        for (int kk = 0; kk < 4; kk++) {
            wmma::fragment<wmma::matrix_a, 16, 16, 16, __nv_bfloat16, wmma::row_major> fah[4], fal[4];
#pragma unroll
            for (int mi = 0; mi < 4; mi++) {
                const __nv_bfloat16* pa = sAh + (wm * 64 + mi * 16) * LDE + kk * 16;
                wmma::load_matrix_sync(fah[mi], pa, LDE);
                wmma::load_matrix_sync(fal[mi], pa + (A_L_OFF - A_H_OFF) / 2, LDE);
            }
#pragma unroll
            for (int nj = 0; nj < 4; nj++) {
                wmma::fragment<wmma::matrix_b, 16, 16, 16, __nv_bfloat16, wmma::col_major> fbh, fbl;
                const __nv_bfloat16* pb = sBh + (wn * 64 + nj * 16) * LDE + kk * 16;
                wmma::load_matrix_sync(fbh, pb, LDE);
                wmma::load_matrix_sync(fbl, pb + (B_L_OFF - B_H_OFF) / 2, LDE);
#pragma unroll
                for (int mi = 0; mi < 4; mi++) {
                    wmma::mma_sync(acc[mi][nj], fah[mi], fbh, acc[mi][nj]);
                    wmma::mma_sync(acc[mi][nj], fah[mi], fbl, acc[mi][nj]);
                    wmma::mma_sync(acc[mi][nj], fal[mi], fbh, acc[mi][nj]);
                }
            }
        }
        __syncthreads();
    }

    // ---- epilogue: stage fp32 C tile [128][260] in smem ----
    float* Cs = (float*)smem;
#pragma unroll
    for (int mi = 0; mi < 4; mi++)
#pragma unroll
        for (int nj = 0; nj < 4; nj++)
            wmma::store_matrix_sync(Cs + (wm * 64 + mi * 16) * LDCE + wn * 64 + nj * 16,
                                    acc[mi][nj], LDCE, wmma::mem_row_major);
    __syncthreads();

    const int r = tid >> 1;
    const int ch = (tid & 1) * 128;
    const int gr = bm + r;
    const float* crow = Cs + r * LDCE + ch;

    if (STAGE == 2) {
        float* po = outf + (size_t)gr * DMOD + nb + ch;
#pragma unroll
        for (int g = 0; g < 32; g++) {
            float4 v = *(const float4*)(crow + g * 4);
            v.x = gelu_exact(v.x); v.y = gelu_exact(v.y);
            v.z = gelu_exact(v.z); v.w = gelu_exact(v.w);
            *(float4*)(po + g * 4) = v;
        }
    } else {
#pragma unroll
        for (int g = 0; g < 16; g++) {
            float v[8];
#pragma unroll
            for (int q = 0; q < 8; q++) v[q] = crow[g * 8 + q];
            size_t gcol = (size_t)gr * SDIM + nb + ch + g * 8;
            if (STAGE == 1) {
                uint4 hres = *(const uint4*)(addh + gcol);
                uint4 lres = *(const uint4*)(addl + gcol);
                const __nv_bfloat16* hp = (const __nv_bfloat16*)&hres;
                const __nv_bfloat16* lp = (const __nv_bfloat16*)&lres;
#pragma unroll
                for (int q = 0; q < 8; q++)
                    v[q] += __bfloat162float(hp[q]) + __bfloat162float(lp[q]);
            }
            __nv_bfloat16 hv[8], lv[8];
#pragma unroll
            for (int q = 0; q < 8; q++) {
                hv[q] = __float2bfloat16(v[q]);
                lv[q] = __float2bfloat16(v[q] - __bfloat162float(hv[q]));
            }
            *(uint4*)(outh + gcol) = *(const uint4*)hv;
            *(uint4*)(outl + gcol) = *(const uint4*)lv;
        }
    }
}

// ---------------------------------------------------------------------------
// LayerNorm over D=1024 per row
// ---------------------------------------------------------------------------
__global__ void ln_kernel(const float* __restrict__ Y,
                          const float* __restrict__ gamma,
                          const float* __restrict__ beta,
                          float* __restrict__ Out)
{
    int r = blockIdx.x;
    const float* row = Y + (size_t)r * DMOD;
    int tid = threadIdx.x;
    float4 v = *(const float4*)(row + tid * 4);
    float s = v.x + v.y + v.z + v.w;
    float sq = v.x * v.x + v.y * v.y + v.z * v.z + v.w * v.w;
#pragma unroll
    for (int o = 16; o > 0; o >>= 1) {
        s  += __shfl_xor_sync(0xffffffffu, s, o);
        sq += __shfl_xor_sync(0xffffffffu, sq, o);
    }
    __shared__ float ws[8], wq[8];
    int w = tid >> 5, l = tid & 31;
    if (l == 0) { ws[w] = s; wq[w] = sq; }
    __syncthreads();
    if (w == 0) {
        float a = (l < 8) ? ws[l] : 0.f;
        float b = (l < 8) ? wq[l] : 0.f;
#pragma unroll
        for (int o = 4; o > 0; o >>= 1) {
            a += __shfl_xor_sync(0xffffffffu, a, o);
            b += __shfl_xor_sync(0xffffffffu, b, o);
        }
        if (l == 0) { ws[0] = a; wq[0] = b; }
    }
    __syncthreads();
    float mean = ws[0] * (1.f / DMOD);
    float var  = wq[0] * (1.f / DMOD) - mean * mean;
    float rstd = rsqrtf(var + 1e-5f);
    float4 g  = *(const float4*)(gamma + tid * 4);
    float4 be = *(const float4*)(beta + tid * 4);
    float4 o;
    o.x = (v.x - mean) * rstd * g.x + be.x;
    o.y = (v.y - mean) * rstd * g.y + be.y;
    o.z = (v.z - mean) * rstd * g.z + be.z;
    o.w = (v.w - mean) * rstd * g.w + be.w;
    *(float4*)(Out + (size_t)r * DMOD + tid * 4) = o;
}

// ---------------------------------------------------------------------------
// kernel_launch
// ---------------------------------------------------------------------------
extern "C" void kernel_launch(void* const* d_in, const int* in_sizes, int n_in,
                              void* d_out, int out_size)
{
    const float* x     = (const float*)d_in[0];
    const float* A     = (const float*)d_in[1];
    const float* Bmat  = (const float*)d_in[2];
    const float* C     = (const float*)d_in[3];
    const float* gamma = (const float*)d_in[4];
    const float* beta  = (const float*)d_in[5];
    float* out = (float*)d_out;

    __nv_bfloat16 *wh0, *wl0, *wh1, *wl1, *Bh, *Bl, *Ch, *Cl, *Ph, *Pl;
    float *P, *Y;
    cudaGetSymbolAddress((void**)&wh0, g_wh);   wh1 = wh0 + (size_t)MROWS * SDIM;
    cudaGetSymbolAddress((void**)&wl0, g_wl);   wl1 = wl0 + (size_t)MROWS * SDIM;
    cudaGetSymbolAddress((void**)&Bh, g_Bh);
    cudaGetSymbolAddress((void**)&Bl, g_Bl);
    cudaGetSymbolAddress((void**)&Ch, g_Ch);
    cudaGetSymbolAddress((void**)&Cl, g_Cl);
    cudaGetSymbolAddress((void**)&P,  g_P);
    cudaGetSymbolAddress((void**)&Ph, g_Ph);
    cudaGetSymbolAddress((void**)&Pl, g_Pl);
    cudaGetSymbolAddress((void**)&Y,  g_Y);

    cudaFuncSetAttribute(mma_gemm<0>, cudaFuncAttributeMaxDynamicSharedMemorySize, SMEM_SZ);
    cudaFuncSetAttribute(mma_gemm<1>, cudaFuncAttributeMaxDynamicSharedMemorySize, SMEM_SZ);
    cudaFuncSetAttribute(mma_gemm<2>, cudaFuncAttributeMaxDynamicSharedMemorySize, SMEM_SZ);

    // ---- prep: weight splits + matrix powers ----
    split_kernel<<<(SDIM * DMOD / 4 + 255) / 256, 256>>>(Bmat, Bh, Bl, SDIM * DMOD / 4);
    split_kernel<<<(DMOD * SDIM / 4 + 255) / 256, 256>>>(C, Ch, Cl, DMOD * SDIM / 4);
    split_kernel<<<(SDIM * SDIM / 4 + 255) / 256, 256>>>(A, Ph, Pl, SDIM * SDIM / 4);
    matsq2<<<dim3(4, 4), 256>>>(A, P);                                  // A^2
    matsq2<<<dim3(4, 4), 256>>>(P, P + SDIM * SDIM);                    // A^4
    matsq2<<<dim3(4, 4), 256>>>(P + SDIM * SDIM, P + 2 * SDIM * SDIM);  // A^8
    for (int i = 0; i < 3; i++)
        split_kernel<<<(SDIM * SDIM / 4 + 255) / 256, 256>>>(
            P + (size_t)i * SDIM * SDIM,
            Ph + (size_t)(i + 1) * SDIM * SDIM,
            Pl + (size_t)(i + 1) * SDIM * SDIM, SDIM * SDIM / 4);

    // ---- GEMM1: u = x @ Bmat^T   [16384 x 256], K=1024, x split fused ----
    mma_gemm<0><<<dim3(1, MROWS / 128), 256, SMEM_SZ>>>(
        x, nullptr, nullptr, Bh, Bl, nullptr, nullptr, wh0, wl0, nullptr, DMOD, 0);

    // ---- scan doubling: w += shift(w, d) @ (A^d)^T,  d = 1,2,4,8 ----
    const int deltas[4] = {1, 2, 4, 8};
    __nv_bfloat16* whp[2] = {wh0, wh1};
    __nv_bfloat16* wlp[2] = {wl0, wl1};
    for (int s = 0; s < 4; s++) {
        __nv_bfloat16* ah = whp[s & 1];       __nv_bfloat16* al = wlp[s & 1];
        __nv_bfloat16* oh = whp[(s + 1) & 1]; __nv_bfloat16* ol = wlp[(s + 1) & 1];
        mma_gemm<1><<<dim3(1, MROWS / 128), 256, SMEM_SZ>>>(
            nullptr, ah, al,
            Ph + (size_t)s * SDIM * SDIM, Pl + (size_t)s * SDIM * SDIM,
            ah, al, oh, ol, nullptr, SDIM, deltas[s]);
    }

    // ---- GEMM2: y = gelu(w @ C^T)   [16384 x 1024], K=256 ----
    mma_gemm<2><<<dim3(DMOD / 256, MROWS / 128), 256, SMEM_SZ>>>(
        nullptr, whp[0], wlp[0], Ch, Cl, nullptr, nullptr, nullptr, nullptr, Y, SDIM, 0);

    // ---- LayerNorm ----
    ln_kernel<<<MROWS, 256>>>(Y, gamma, beta, out);
}

// round 5
// speedup vs baseline: 1.9776x; 1.1373x over previous
#include <cuda_runtime.h>
#include <cuda_bf16.h>
#include <math.h>
#include <stdint.h>

#define BSZ   8
#define LSEQ  2048
#define DMOD  1024
#define SDIM  256
#define MROWS (BSZ*LSEQ)   // 16384

// ---------------------------------------------------------------------------
// Static device scratch
// ---------------------------------------------------------------------------
__device__ __align__(128) __nv_bfloat16 g_wh[2][(size_t)MROWS * SDIM];
__device__ __align__(128) __nv_bfloat16 g_wl[2][(size_t)MROWS * SDIM];
__device__ __align__(128) __nv_bfloat16 g_Bh[SDIM * DMOD];
__device__ __align__(128) __nv_bfloat16 g_Bl[SDIM * DMOD];
__device__ __align__(128) __nv_bfloat16 g_Ch[DMOD * SDIM];
__device__ __align__(128) __nv_bfloat16 g_Cl[DMOD * SDIM];
__device__ __align__(128) float         g_P[3][SDIM * SDIM];      // A^2,A^4,A^8
__device__ __align__(128) __nv_bfloat16 g_Ph[4][SDIM * SDIM];     // A,A2,A4,A8 hi
__device__ __align__(128) __nv_bfloat16 g_Pl[4][SDIM * SDIM];     // lo
__device__ __align__(128) float         g_Y[(size_t)MROWS * DMOD];

// ---------------------------------------------------------------------------
// PTX helpers (base sm_80+ ISA only)
// ---------------------------------------------------------------------------
__device__ __forceinline__ uint32_t smem_u32(const void* p) {
    uint32_t a;
    asm("{ .reg .u64 t; cvta.to.shared.u64 t, %1; cvt.u32.u64 %0, t; }" : "=r"(a) : "l"(p));
    return a;
}
__device__ __forceinline__ void cp16(uint32_t s, const void* g) {
    asm volatile("cp.async.cg.shared.global [%0], [%1], 16;" :: "r"(s), "l"(g));
}
__device__ __forceinline__ void cp16z(uint32_t s, const void* g, int sz) {
    asm volatile("cp.async.cg.shared.global [%0], [%1], 16, %2;" :: "r"(s), "l"(g), "r"(sz));
}
#define CP_COMMIT()   asm volatile("cp.async.commit_group;" ::: "memory")
#define CP_WAIT(n)    asm volatile("cp.async.wait_group %0;" :: "n"(n) : "memory")

__device__ __forceinline__ void ldm_x4(uint32_t* r, uint32_t saddr) {
    asm volatile("ldmatrix.sync.aligned.m8n8.x4.shared.b16 {%0,%1,%2,%3}, [%4];"
        : "=r"(r[0]), "=r"(r[1]), "=r"(r[2]), "=r"(r[3]) : "r"(saddr));
}
__device__ __forceinline__ void mma16816(float* c, const uint32_t* a, const uint32_t* b) {
    asm volatile("mma.sync.aligned.m16n8k16.row.col.f32.bf16.bf16.f32 "
        "{%0,%1,%2,%3}, {%4,%5,%6,%7}, {%8,%9}, {%0,%1,%2,%3};"
        : "+f"(c[0]), "+f"(c[1]), "+f"(c[2]), "+f"(c[3])
        : "r"(a[0]), "r"(a[1]), "r"(a[2]), "r"(a[3]), "r"(b[0]), "r"(b[1]));
}

__device__ __forceinline__ float gelu_exact(float x) {
    return 0.5f * x * (1.0f + erff(x * 0.7071067811865476f));
}

// ---------------------------------------------------------------------------
// fp32 -> (hi, lo) bf16 split (weights / matrix powers)
// ---------------------------------------------------------------------------
__global__ void split_kernel(const float* __restrict__ in,
                             __nv_bfloat16* __restrict__ h,
                             __nv_bfloat16* __restrict__ l, int n4) {
    int i = blockIdx.x * blockDim.x + threadIdx.x;
    if (i >= n4) return;
    float4 v = ((const float4*)in)[i];
    __nv_bfloat16 h0 = __float2bfloat16(v.x), h1 = __float2bfloat16(v.y);
    __nv_bfloat16 h2 = __float2bfloat16(v.z), h3 = __float2bfloat16(v.w);
    __nv_bfloat16 l0 = __float2bfloat16(v.x - __bfloat162float(h0));
    __nv_bfloat16 l1 = __float2bfloat16(v.y - __bfloat162float(h1));
    __nv_bfloat16 l2 = __float2bfloat16(v.z - __bfloat162float(h2));
    __nv_bfloat16 l3 = __float2bfloat16(v.w - __bfloat162float(h3));
    uint2 hv, lv;
    hv.x = (uint32_t)__bfloat16_as_ushort(h0) | ((uint32_t)__bfloat16_as_ushort(h1) << 16);
    hv.y = (uint32_t)__bfloat16_as_ushort(h2) | ((uint32_t)__bfloat16_as_ushort(h3) << 16);
    lv.x = (uint32_t)__bfloat16_as_ushort(l0) | ((uint32_t)__bfloat16_as_ushort(l1) << 16);
    lv.y = (uint32_t)__bfloat16_as_ushort(l2) | ((uint32_t)__bfloat16_as_ushort(l3) << 16);
    ((uint2*)h)[i] = hv;
    ((uint2*)l)[i] = lv;
}

__global__ void zero_kernel(float* __restrict__ p) {
    p[blockIdx.x * 256 + threadIdx.x] = 0.f;
}

// ---------------------------------------------------------------------------
// Split-K fp32 matrix square: Out += In@In chunk. grid (4,4,4): 64x64 tile, K=64.
// Out must be zeroed first.
// ---------------------------------------------------------------------------
__global__ __launch_bounds__(256) void matsq_sk(const float* __restrict__ In,
                                                float* __restrict__ Out) {
    __shared__ float sA[64][65];
    __shared__ float sB[64][65];
    const int tid = threadIdx.x;
    const int i0 = blockIdx.y * 64, j0 = blockIdx.x * 64, k0 = blockIdx.z * 64;
#pragma unroll
    for (int i = 0; i < 16; i++) {
        int e = tid + i * 256;
        int r = e >> 6, c = e & 63;
        sA[r][c] = In[(i0 + r) * SDIM + k0 + c];
        sB[r][c] = In[(k0 + r) * SDIM + j0 + c];
    }
    __syncthreads();
    const int ty = tid >> 4, tx = tid & 15;
    float acc[4][4] = {};
#pragma unroll 16
    for (int k = 0; k < 64; k++) {
        float a[4], b[4];
#pragma unroll
        for (int q = 0; q < 4; q++) a[q] = sA[ty * 4 + q][k];
#pragma unroll
        for (int q = 0; q < 4; q++) b[q] = sB[k][tx * 4 + q];
#pragma unroll
        for (int q = 0; q < 4; q++)
#pragma unroll
            for (int r = 0; r < 4; r++) acc[q][r] = fmaf(a[q], b[r], acc[q][r]);
    }
#pragma unroll
    for (int q = 0; q < 4; q++)
#pragma unroll
        for (int r = 0; r < 4; r++)
            atomicAdd(&Out[(i0 + ty * 4 + q) * SDIM + j0 + tx * 4 + r], acc[q][r]);
}

// ---------------------------------------------------------------------------
// GEMM: C[128 x 256] = A[M,K] @ B[N,K]^T, split-bf16 3-term, fp32 acc.
// ldmatrix + mma.m16n8k16, cp.async double buffer, 8 warps, warp tile 64x64.
//   STAGE 0: A = x fp32 (split in loader), out -> bf16 hi/lo
//   STAGE 1: A = bf16 hi/lo shifted by delta, out = acc + u -> bf16 hi/lo
//   STAGE 2: out = gelu(acc) -> fp32 (width DMOD)
// ---------------------------------------------------------------------------
#define BKQ      64
#define LROW     144
#define A_H_OFF  0
#define A_L_OFF  18432
#define B_H_OFF  36864
#define B_L_OFF  73728
#define STAGE_B  110592
#define SMEM_SZ  (2 * STAGE_B)
#define LDCE     260

template <int STAGE>
__global__ __launch_bounds__(256, 1) void mma_gemm(
    const float* __restrict__ Xf,
    const __nv_bfloat16* __restrict__ Ah, const __nv_bfloat16* __restrict__ Al,
    const __nv_bfloat16* __restrict__ Bh, const __nv_bfloat16* __restrict__ Bl,
    const __nv_bfloat16* __restrict__ addh, const __nv_bfloat16* __restrict__ addl,
    __nv_bfloat16* __restrict__ outh, __nv_bfloat16* __restrict__ outl,
    float* __restrict__ outf,
    int K, int delta)
{
    extern __shared__ char smem[];
    const int tid = threadIdx.x;
    const int bm = blockIdx.y * 128;
    const int nb = blockIdx.x * 256;
    const int NC = K / BKQ;
    const uint32_t sb = smem_u32(smem);

    const int w    = tid >> 5;
    const int lane = tid & 31;
    const int wm = w & 1;          // 2 m-positions x 64
    const int wn = w >> 1;         // 4 n-positions x 64

    // ldmatrix per-lane address components
    const int lt = lane >> 3, lr = lane & 7;
    const uint32_t aLane = (uint32_t)(((lt & 1) * 8 + lr) * LROW + (lt >> 1) * 16);
    const uint32_t bLane = (uint32_t)(((lt >> 1) * 8 + lr) * LROW + (lt & 1) * 16);

    float acc[4][8][4];
#pragma unroll
    for (int i = 0; i < 4; i++)
#pragma unroll
        for (int j = 0; j < 8; j++)
#pragma unroll
            for (int q = 0; q < 4; q++) acc[i][j][q] = 0.f;

    auto load_tile = [&](int c, int buf) {
        const uint32_t base = sb + buf * STAGE_B;
        const int k0 = c * BKQ;
        if (STAGE == 0) {
#pragma unroll
            for (int i = 0; i < 8; i++) {
                int e = tid + i * 256;
                int row = e >> 4, cg = e & 15;
                float4 v = *(const float4*)(Xf + (size_t)(bm + row) * K + k0 + cg * 4);
                __nv_bfloat16 h0 = __float2bfloat16(v.x), h1 = __float2bfloat16(v.y);
                __nv_bfloat16 h2 = __float2bfloat16(v.z), h3 = __float2bfloat16(v.w);
                __nv_bfloat16 l0 = __float2bfloat16(v.x - __bfloat162float(h0));
                __nv_bfloat16 l1 = __float2bfloat16(v.y - __bfloat162float(h1));
                __nv_bfloat16 l2 = __float2bfloat16(v.z - __bfloat162float(h2));
                __nv_bfloat16 l3 = __float2bfloat16(v.w - __bfloat162float(h3));
                uint2 hv, lv;
                hv.x = (uint32_t)__bfloat16_as_ushort(h0) | ((uint32_t)__bfloat16_as_ushort(h1) << 16);
                hv.y = (uint32_t)__bfloat16_as_ushort(h2) | ((uint32_t)__bfloat16_as_ushort(h3) << 16);
                lv.x = (uint32_t)__bfloat16_as_ushort(l0) | ((uint32_t)__bfloat16_as_ushort(l1) << 16);
                lv.y = (uint32_t)__bfloat16_as_ushort(l2) | ((uint32_t)__bfloat16_as_ushort(l3) << 16);
                uint32_t so = row * LROW + cg * 8;
                *(uint2*)(smem + buf * STAGE_B + A_H_OFF + so) = hv;
                *(uint2*)(smem + buf * STAGE_B + A_L_OFF + so) = lv;
            }
        } else {
#pragma unroll
            for (int i = 0; i < 4; i++) {
                int e = tid + i * 256;
                int row = e >> 3, kc = e & 7;
                int gr = bm + row;
                int t = gr & (LSEQ - 1);
                int sz = (t >= delta) ? 16 : 0;
                int srow = gr - (t >= delta ? delta : 0);
                size_t go = (size_t)srow * K + k0 + kc * 8;
                uint32_t so = base + row * LROW + kc * 16;
                cp16z(so + A_H_OFF, Ah + go, sz);
                cp16z(so + A_L_OFF, Al + go, sz);
            }
        }
#pragma unroll
        for (int i = 0; i < 8; i++) {
            int e = tid + i * 256;
            int row = e >> 3, kc = e & 7;
            size_t go = (size_t)(nb + row) * K + k0 + kc * 8;
            uint32_t so = base + row * LROW + kc * 16;
            cp16(so + B_H_OFF, Bh + go);
            cp16(so + B_L_OFF, Bl + go);
        }
        CP_COMMIT();
    };

    load_tile(0, 0);

    for (int c = 0; c < NC; c++) {
        const int b = c & 1;
        if (c + 1 < NC) { load_tile(c + 1, b ^ 1); CP_WAIT(1); }
        else            { CP_WAIT(0); }
        __syncthreads();

        const uint32_t aBase = sb + b * STAGE_B + A_H_OFF + (wm * 64) * LROW + aLane;
        const uint32_t bBase = sb + b * STAGE_B + B_H_OFF + (wn * 64) * LROW + bLane;

#pragma unroll
        for (int kk = 0; kk < 4; kk++) {
            uint32_t ah[4][4], al[4][4];
#pragma unroll
            for (int mi = 0; mi < 4; mi++) {
                uint32_t a0 = aBase + mi * (16 * LROW) + kk * 32;
                ldm_x4(ah[mi], a0);
                ldm_x4(al[mi], a0 + (A_L_OFF - A_H_OFF));
            }
#pragma unroll
            for (int g = 0; g < 4; g++) {
                uint32_t bh[4], bl[4];
                uint32_t b0 = bBase + g * (16 * LROW) + kk * 32;
                ldm_x4(bh, b0);
                ldm_x4(bl, b0 + (B_L_OFF - B_H_OFF));
#pragma unroll
                for (int mi = 0; mi < 4; mi++) {
                    mma16816(acc[mi][2 * g],     ah[mi], bh);
                    mma16816(acc[mi][2 * g],     ah[mi], bl);
                    mma16816(acc[mi][2 * g],     al[mi], bh);
                    mma16816(acc[mi][2 * g + 1], ah[mi], bh + 2);
                    mma16816(acc[mi][2 * g + 1], ah[mi], bl + 2);
                    mma16816(acc[mi][2 * g + 1], al[mi], bh + 2);
                }
            }
        }
        __syncthreads();
    }

    // ---- epilogue: stage fp32 C tile [128][260] through smem ----
    float* Cs = (float*)smem;
    const int g4 = lane >> 2, tig = lane & 3;
#pragma unroll
    for (int mi = 0; mi < 4; mi++)
#pragma unroll
        for (int nj = 0; nj < 8; nj++) {
            int row = wm * 64 + mi * 16 + g4;
            int col = wn * 64 + nj * 8 + tig * 2;
            *(float2*)(Cs + row * LDCE + col)       = make_float2(acc[mi][nj][0], acc[mi][nj][1]);
            *(float2*)(Cs + (row + 8) * LDCE + col) = make_float2(acc[mi][nj][2], acc[mi][nj][3]);
        }
    __syncthreads();

    const int r = tid >> 1;
    const int ch = (tid & 1) * 128;
    const int gr = bm + r;
    const float* crow = Cs + r * LDCE + ch;

    if (STAGE == 2) {
        float* po = outf + (size_t)gr * DMOD + nb + ch;
#pragma unroll
        for (int g = 0; g < 32; g++) {
            float4 v = *(const float4*)(crow + g * 4);
            v.x = gelu_exact(v.x); v.y = gelu_exact(v.y);
            v.z = gelu_exact(v.z); v.w = gelu_exact(v.w);
            *(float4*)(po + g * 4) = v;
        }
    } else {
#pragma unroll
        for (int g = 0; g < 16; g++) {
            float v[8];
#pragma unroll
            for (int q = 0; q < 8; q++) v[q] = crow[g * 8 + q];
            size_t gcol = (size_t)gr * SDIM + nb + ch + g * 8;
            if (STAGE == 1) {
                uint4 hres = *(const uint4*)(addh + gcol);
                uint4 lres = *(const uint4*)(addl + gcol);
                const __nv_bfloat16* hp = (const __nv_bfloat16*)&hres;
                const __nv_bfloat16* lp = (const __nv_bfloat16*)&lres;
#pragma unroll
                for (int q = 0; q < 8; q++)
                    v[q] += __bfloat162float(hp[q]) + __bfloat162float(lp[q]);
            }
            __nv_bfloat16 hv[8], lv[8];
#pragma unroll
            for (int q = 0; q < 8; q++) {
                hv[q] = __float2bfloat16(v[q]);
                lv[q] = __float2bfloat16(v[q] - __bfloat162float(hv[q]));
            }
            *(uint4*)(outh + gcol) = *(const uint4*)hv;
            *(uint4*)(outl + gcol) = *(const uint4*)lv;
        }
    }
}

// ---------------------------------------------------------------------------
// LayerNorm over D=1024 per row
// ---------------------------------------------------------------------------
__global__ void ln_kernel(const float* __restrict__ Y,
                          const float* __restrict__ gamma,
                          const float* __restrict__ beta,
                          float* __restrict__ Out)
{
    int r = blockIdx.x;
    const float* row = Y + (size_t)r * DMOD;
    int tid = threadIdx.x;
    float4 v = *(const float4*)(row + tid * 4);
    float s = v.x + v.y + v.z + v.w;
    float sq = v.x * v.x + v.y * v.y + v.z * v.z + v.w * v.w;
#pragma unroll
    for (int o = 16; o > 0; o >>= 1) {
        s  += __shfl_xor_sync(0xffffffffu, s, o);
        sq += __shfl_xor_sync(0xffffffffu, sq, o);
    }
    __shared__ float ws[8], wq[8];
    int w = tid >> 5, l = tid & 31;
    if (l == 0) { ws[w] = s; wq[w] = sq; }
    __syncthreads();
    if (w == 0) {
        float a = (l < 8) ? ws[l] : 0.f;
        float b = (l < 8) ? wq[l] : 0.f;
#pragma unroll
        for (int o = 4; o > 0; o >>= 1) {
            a += __shfl_xor_sync(0xffffffffu, a, o);
            b += __shfl_xor_sync(0xffffffffu, b, o);
        }
        if (l == 0) { ws[0] = a; wq[0] = b; }
    }
    __syncthreads();
    float mean = ws[0] * (1.f / DMOD);
    float var  = wq[0] * (1.f / DMOD) - mean * mean;
    float rstd = rsqrtf(var + 1e-5f);
    float4 g  = *(const float4*)(gamma + tid * 4);
    float4 be = *(const float4*)(beta + tid * 4);
    float4 o;
    o.x = (v.x - mean) * rstd * g.x + be.x;
    o.y = (v.y - mean) * rstd * g.y + be.y;
    o.z = (v.z - mean) * rstd * g.z + be.z;
    o.w = (v.w - mean) * rstd * g.w + be.w;
    *(float4*)(Out + (size_t)r * DMOD + tid * 4) = o;
}

// ---------------------------------------------------------------------------
// kernel_launch
// ---------------------------------------------------------------------------
extern "C" void kernel_launch(void* const* d_in, const int* in_sizes, int n_in,
                              void* d_out, int out_size)
{
    const float* x     = (const float*)d_in[0];
    const float* A     = (const float*)d_in[1];
    const float* Bmat  = (const float*)d_in[2];
    const float* C     = (const float*)d_in[3];
    const float* gamma = (const float*)d_in[4];
    const float* beta  = (const float*)d_in[5];
    float* out = (float*)d_out;

    __nv_bfloat16 *wh0, *wl0, *wh1, *wl1, *Bh, *Bl, *Ch, *Cl, *Ph, *Pl;
    float *P, *Y;
    cudaGetSymbolAddress((void**)&wh0, g_wh);   wh1 = wh0 + (size_t)MROWS * SDIM;
    cudaGetSymbolAddress((void**)&wl0, g_wl);   wl1 = wl0 + (size_t)MROWS * SDIM;
    cudaGetSymbolAddress((void**)&Bh, g_Bh);
    cudaGetSymbolAddress((void**)&Bl, g_Bl);
    cudaGetSymbolAddress((void**)&Ch, g_Ch);
    cudaGetSymbolAddress((void**)&Cl, g_Cl);
    cudaGetSymbolAddress((void**)&P,  g_P);
    cudaGetSymbolAddress((void**)&Ph, g_Ph);
    cudaGetSymbolAddress((void**)&Pl, g_Pl);
    cudaGetSymbolAddress((void**)&Y,  g_Y);

    cudaFuncSetAttribute(mma_gemm<0>, cudaFuncAttributeMaxDynamicSharedMemorySize, SMEM_SZ);
    cudaFuncSetAttribute(mma_gemm<1>, cudaFuncAttributeMaxDynamicSharedMemorySize, SMEM_SZ);
    cudaFuncSetAttribute(mma_gemm<2>, cudaFuncAttributeMaxDynamicSharedMemorySize, SMEM_SZ);

    // ---- prep: weight splits + matrix powers (split-K + atomics) ----
    split_kernel<<<(SDIM * DMOD / 4 + 255) / 256, 256>>>(Bmat, Bh, Bl, SDIM * DMOD / 4);
    split_kernel<<<(DMOD * SDIM / 4 + 255) / 256, 256>>>(C, Ch, Cl, DMOD * SDIM / 4);
    split_kernel<<<(SDIM * SDIM / 4 + 255) / 256, 256>>>(A, Ph, Pl, SDIM * SDIM / 4);
    zero_kernel<<<3 * SDIM * SDIM / 256, 256>>>(P);
    const dim3 skgrid(4, 4, 4);
    matsq_sk<<<skgrid, 256>>>(A, P);
    split_kernel<<<SDIM * SDIM / 4 / 256, 256>>>(P, Ph + SDIM * SDIM, Pl + SDIM * SDIM, SDIM * SDIM / 4);
    matsq_sk<<<skgrid, 256>>>(P, P + SDIM * SDIM);
    split_kernel<<<SDIM * SDIM / 4 / 256, 256>>>(P + SDIM * SDIM, Ph + 2 * SDIM * SDIM, Pl + 2 * SDIM * SDIM, SDIM * SDIM / 4);
    matsq_sk<<<skgrid, 256>>>(P + SDIM * SDIM, P + 2 * SDIM * SDIM);
    split_kernel<<<SDIM * SDIM / 4 / 256, 256>>>(P + 2 * SDIM * SDIM, Ph + 3 * SDIM * SDIM, Pl + 3 * SDIM * SDIM, SDIM * SDIM / 4);

    // ---- GEMM1: u = x @ Bmat^T   [16384 x 256], K=1024, x split fused ----
    mma_gemm<0><<<dim3(1, MROWS / 128), 256, SMEM_SZ>>>(
        x, nullptr, nullptr, Bh, Bl, nullptr, nullptr, wh0, wl0, nullptr, DMOD, 0);

    // ---- scan doubling: w += shift(w, d) @ (A^d)^T,  d = 1,2,4,8 ----
    const int deltas[4] = {1, 2, 4, 8};
    __nv_bfloat16* whp[2] = {wh0, wh1};
    __nv_bfloat16* wlp[2] = {wl0, wl1};
    for (int s = 0; s < 4; s++) {
        __nv_bfloat16* ah = whp[s & 1];       __nv_bfloat16* al = wlp[s & 1];
        __nv_bfloat16* oh = whp[(s + 1) & 1]; __nv_bfloat16* ol = wlp[(s + 1) & 1];
        mma_gemm<1><<<dim3(1, MROWS / 128), 256, SMEM_SZ>>>(
            nullptr, ah, al,
            Ph + (size_t)s * SDIM * SDIM, Pl + (size_t)s * SDIM * SDIM,
            ah, al, oh, ol, nullptr, SDIM, deltas[s]);
    }

    // ---- GEMM2: y = gelu(w @ C^T)   [16384 x 1024], K=256 ----
    mma_gemm<2><<<dim3(DMOD / 256, MROWS / 128), 256, SMEM_SZ>>>(
        nullptr, whp[0], wlp[0], Ch, Cl, nullptr, nullptr, nullptr, nullptr, Y, SDIM, 0);

    // ---- LayerNorm ----
    ln_kernel<<<MROWS, 256>>>(Y, gamma, beta, out);
}